// round 16
// baseline (speedup 1.0000x reference)
#include <cuda_runtime.h>
#include <cuda_bf16.h>
#include <math.h>

#define E    512
#define HH   1536
#define G4   6144
#define SS   32
#define TT   48
#define NV   128
#define NB   128       // persistent blocks (1/SM)
#define NT   512       // 16 warps
#define UPB  12        // h2/c2 units per block
#define RPB  48        // gate rows / whh1 rows per block
#define KU   3         // h-vector elems per thread (HH/NT)
#define LSTR 64        // logit slot stride (256B)
#define FSTR 32        // flag slot stride (128B)
#define WELEM (G4 * HH)

typedef unsigned long long u64;

// ---------------- persistent device state ----------------
__device__ float          g_xproj[NV * G4];            // W_ih1@emb[v] + b_ih1 + b_hh1
__device__ __nv_bfloat16  g_w2cat[(size_t)G4 * 2 * HH];// [W_ih2 | W_hh2] rows of 3072
__device__ __nv_bfloat16  g_whh1[WELEM];
__device__ float          g_c1[2][HH];
__device__ float          g_c2[HH];
__device__ float          g_h2[2][HH];
__device__ float          g_g1[2][G4];                 // W_hh1 @ h1(t), double buffered
__device__ float          g_log3[3][SS * LSTR];        // triple-buffered padded logits
__device__ unsigned       g_flags[NB * FSTR];          // monotonic epochs (never reset)

__device__ __forceinline__ float fsigm(float x) {
    return __fdividef(1.0f, 1.0f + __expf(-x));
}
__device__ __forceinline__ float ftanh(float x) {
    x = fminf(fmaxf(x, -15.0f), 15.0f);
    float e = __expf(2.0f * x);
    return __fdividef(e - 1.0f, e + 1.0f);
}
__device__ __forceinline__ float warpsum(float v) {
    #pragma unroll
    for (int o = 16; o; o >>= 1) v += __shfl_down_sync(0xffffffffu, v, o);
    return v;
}

// ---- packed f32x2 helpers (sm_100+) ----
__device__ __forceinline__ u64 f2pack(float x, float y) {
    u64 r; asm("mov.b64 %0, {%1, %2};" : "=l"(r) : "f"(x), "f"(y)); return r;
}
__device__ __forceinline__ float f2sum(u64 v) {
    float x, y; asm("mov.b64 {%0, %1}, %2;" : "=f"(x), "=f"(y) : "l"(v));
    return x + y;
}
__device__ __forceinline__ u64 bf2f2(unsigned q) {   // bf16x2 -> (f32,f32)
    unsigned lo = q << 16, hi = q & 0xFFFF0000u;
    u64 r; asm("mov.b64 %0, {%1, %2};" : "=l"(r) : "r"(lo), "r"(hi)); return r;
}
__device__ __forceinline__ u64 ffma2(u64 a, u64 b, u64 c) {
    u64 d; asm("fma.rn.f32x2 %0, %1, %2, %3;" : "=l"(d) : "l"(a), "l"(b), "l"(c));
    return d;
}

// NOTE: parameters m0..m3 so the .x/.y/.z/.w member accesses are not captured
#define ACC8(acc, q, m0, m1, m2, m3) \
    p = bf2f2((q).x); acc = ffma2(p, m0, acc); \
    p = bf2f2((q).y); acc = ffma2(p, m1, acc); \
    p = bf2f2((q).z); acc = ffma2(p, m2, acc); \
    p = bf2f2((q).w); acc = ffma2(p, m3, acc);

// MEGADOT: 3 rows of W_hh2 against h2-vector, 3 rows of W_ih2 + 3 rows of
// W_hh1 against h1-vector — all in ONE pass (11 load streams / seg).
template<int SEGS>
__device__ __forceinline__ void dot9_acc(const __nv_bfloat16* __restrict__ w2b,
                                         const __nv_bfloat16* __restrict__ w1b,
                                         const float* __restrict__ svh1,
                                         const float* __restrict__ svh2,
                                         int lane, float* aA, float* aC) {
    u64 pa0 = 0ull, pa1 = 0ull, pa2 = 0ull;   // W_hh2 @ h2
    u64 pb0 = 0ull, pb1 = 0ull, pb2 = 0ull;   // W_ih2 @ h1
    u64 pc0 = 0ull, pc1 = 0ull, pc2 = 0ull;   // W_hh1 @ h1
    #pragma unroll
    for (int j = 0; j < SEGS; j++) {
        int seg = lane + 32 * j;
        const float4* v1 = (const float4*)(svh1 + seg * 8);
        const float4* v2 = (const float4*)(svh2 + seg * 8);
        float4 h1a = v1[0], h1b = v1[1];
        float4 h2a = v2[0], h2b = v2[1];
        u64 u10 = f2pack(h1a.x, h1a.y), u11 = f2pack(h1a.z, h1a.w);
        u64 u12 = f2pack(h1b.x, h1b.y), u13 = f2pack(h1b.z, h1b.w);
        u64 u20 = f2pack(h2a.x, h2a.y), u21 = f2pack(h2a.z, h2a.w);
        u64 u22 = f2pack(h2b.x, h2b.y), u23 = f2pack(h2b.z, h2b.w);
        // 9 independent weight streams
        uint4 qa0 = __ldg((const uint4*)(w2b + HH) + seg);              // hh2 r0
        uint4 qa1 = __ldg((const uint4*)(w2b + HH + 2 * HH) + seg);    // hh2 r1
        uint4 qa2 = __ldg((const uint4*)(w2b + HH + 4 * HH) + seg);    // hh2 r2
        uint4 qb0 = __ldg((const uint4*)(w2b) + seg);                  // ih2 r0
        uint4 qb1 = __ldg((const uint4*)(w2b + 2 * HH) + seg);         // ih2 r1
        uint4 qb2 = __ldg((const uint4*)(w2b + 4 * HH) + seg);         // ih2 r2
        uint4 qc0 = __ldg((const uint4*)(w1b) + seg);                  // hh1 r0
        uint4 qc1 = __ldg((const uint4*)(w1b + HH) + seg);             // hh1 r1
        uint4 qc2 = __ldg((const uint4*)(w1b + 2 * HH) + seg);         // hh1 r2
        u64 p;
        ACC8(pa0, qa0, u20, u21, u22, u23)
        ACC8(pa1, qa1, u20, u21, u22, u23)
        ACC8(pa2, qa2, u20, u21, u22, u23)
        ACC8(pb0, qb0, u10, u11, u12, u13)
        ACC8(pb1, qb1, u10, u11, u12, u13)
        ACC8(pb2, qb2, u10, u11, u12, u13)
        ACC8(pc0, qc0, u10, u11, u12, u13)
        ACC8(pc1, qc1, u10, u11, u12, u13)
        ACC8(pc2, qc2, u10, u11, u12, u13)
    }
    aA[0] = f2sum(pa0) + f2sum(pb0);   // gate row = hh2 + ih2
    aA[1] = f2sum(pa1) + f2sum(pb1);
    aA[2] = f2sum(pa2) + f2sum(pb2);
    aC[0] = f2sum(pc0);
    aC[1] = f2sum(pc1);
    aC[2] = f2sum(pc2);
}

// symmetric grid barrier: padded per-block flags, first NB threads poll
__device__ __forceinline__ void grid_sync(int b, unsigned ep) {
    __threadfence();
    __syncthreads();
    if (threadIdx.x == 0)
        *(volatile unsigned*)&g_flags[b * FSTR] = ep;
    if (threadIdx.x < NB) {
        volatile unsigned* f = &g_flags[threadIdx.x * FSTR];
        while ((int)(*f - ep) < 0) { __nanosleep(64); }
    }
    __syncthreads();
    __threadfence();
}

// ================== the one and only kernel ==================
__global__ void __launch_bounds__(NT, 1)
nas_all(const int*   __restrict__ input_id,
        const float* __restrict__ emb,
        const float* __restrict__ Wih1,
        const float* __restrict__ Whh1f,
        const float* __restrict__ bih1, const float* __restrict__ bhh1,
        const float* __restrict__ Wih2f,
        const float* __restrict__ Whh2f,
        const float* __restrict__ bih2, const float* __restrict__ bhh2,
        const float* __restrict__ Wout,
        const float* __restrict__ bout,
        float* __restrict__ out) {
    __shared__ __align__(16) float sMem[16 * (E + 8)];   // 33.3 KB; aliased
    float* sV  = sMem;                        // loop: [h1 ; h2] (3072)
    float* sWo = sMem + 2 * HH;               // loop: head slice (384)
    float* sG  = sMem + 2 * HH + SS * UPB;    // loop: gates (48)
    __shared__ unsigned sBase;

    const int tid  = threadIdx.x;
    const int w    = tid >> 5;
    const int lane = tid & 31;
    const int b    = blockIdx.x;
    const int u0   = b * UPB;

    // warp row assignments (3 rows/warp; 3|12 so never crosses a gate boundary)
    const int l0   = 3 * w;                   // 0..45
    const int gate = l0 / UPB;
    const int j0   = l0 % UPB;
    const int grow = gate * HH + u0 + j0;
    const __nv_bfloat16* w2base = g_w2cat + (size_t)grow * (2 * HH);
    const int r1row = b * RPB + l0;
    const __nv_bfloat16* w1base = g_whh1 + (size_t)r1row * HH;
    const float bsum0 = __ldg(&bih2[grow])     + __ldg(&bhh2[grow]);
    const float bsum1 = __ldg(&bih2[grow + 1]) + __ldg(&bhh2[grow + 1]);
    const float bsum2 = __ldg(&bih2[grow + 2]) + __ldg(&bhh2[grow + 2]);

    // ---- epoch base (flags monotonic across graph replays) ----
    if (tid == 0) sBase = g_flags[b * FSTR];
    __syncthreads();
    const unsigned base = sBase;

    // ======== PROLOGUE (distributed by block) ========
    if (tid < UPB) { g_c2[u0 + tid] = 0.f; g_h2[0][u0 + tid] = 0.f; }

    // bf16-convert own RPB rows of W_ih2 / W_hh2 (into concat) and W_hh1
    {
        const size_t r0 = (size_t)b * RPB;
        #pragma unroll
        for (int m = 0; m < 3; m++) {
            const float* src = (m == 0) ? Wih2f : (m == 1) ? Whh2f : Whh1f;
            for (int idx = tid; idx < RPB * HH / 8; idx += NT) {
                size_t e = (size_t)idx * 8;
                size_t row = r0 + e / HH, col = e % HH;
                const float* s = src + row * HH + col;
                float4 a = *(const float4*)s;
                float4 c = *(const float4*)(s + 4);
                __nv_bfloat162 q0 = __floats2bfloat162_rn(a.x, a.y);
                __nv_bfloat162 q1 = __floats2bfloat162_rn(a.z, a.w);
                __nv_bfloat162 q2 = __floats2bfloat162_rn(c.x, c.y);
                __nv_bfloat162 q3 = __floats2bfloat162_rn(c.z, c.w);
                uint4 o;
                o.x = *(unsigned*)&q0; o.y = *(unsigned*)&q1;
                o.z = *(unsigned*)&q2; o.w = *(unsigned*)&q3;
                __nv_bfloat16* d = (m == 2)
                    ? (g_whh1 + row * HH + col)
                    : (g_w2cat + row * (2 * HH) + (m == 1 ? HH : 0) + col);
                *(uint4*)d = o;
            }
        }
    }

    // xproj: own rows r, r+1, r+2 (per warp) for all 128 embeddings
    {
        const int r = b * RPB + w * 3;
        u64 wa[8], wb[8], wc[8];
        {
            const float4* wra = (const float4*)(Wih1 + (size_t)r * E);
            const float4* wrb = (const float4*)(Wih1 + (size_t)(r + 1) * E);
            const float4* wrc = (const float4*)(Wih1 + (size_t)(r + 2) * E);
            #pragma unroll
            for (int i = 0; i < 4; i++) {
                float4 A = __ldg(&wra[lane * 4 + i]);
                float4 B = __ldg(&wrb[lane * 4 + i]);
                float4 C = __ldg(&wrc[lane * 4 + i]);
                wa[2 * i] = f2pack(A.x, A.y); wa[2 * i + 1] = f2pack(A.z, A.w);
                wb[2 * i] = f2pack(B.x, B.y); wb[2 * i + 1] = f2pack(B.z, B.w);
                wc[2 * i] = f2pack(C.x, C.y); wc[2 * i + 1] = f2pack(C.z, C.w);
            }
        }
        const float bs0 = __ldg(&bih1[r])     + __ldg(&bhh1[r]);
        const float bs1 = __ldg(&bih1[r + 1]) + __ldg(&bhh1[r + 1]);
        const float bs2 = __ldg(&bih1[r + 2]) + __ldg(&bhh1[r + 2]);

        for (int c = 0; c < NV / 16; c++) {
            __syncthreads();
            for (int idx = tid; idx < 16 * (E / 4); idx += NT) {
                int v = idx >> 7, e4 = idx & 127;
                float4 d = __ldg((const float4*)(emb + (size_t)(c * 16 + v) * E) + e4);
                *(float4*)&sMem[v * (E + 8) + e4 * 4] = d;
            }
            __syncthreads();
            #pragma unroll 2
            for (int v = 0; v < 16; v++) {
                const float* ev = &sMem[v * (E + 8) + lane * 16];
                u64 s0 = 0ull, s1 = 0ull, s2 = 0ull;
                #pragma unroll
                for (int i = 0; i < 4; i++) {
                    float4 x = *(const float4*)(ev + 4 * i);
                    u64 x0 = f2pack(x.x, x.y), x1 = f2pack(x.z, x.w);
                    s0 = ffma2(wa[2 * i], x0, s0);
                    s0 = ffma2(wa[2 * i + 1], x1, s0);
                    s1 = ffma2(wb[2 * i], x0, s1);
                    s1 = ffma2(wb[2 * i + 1], x1, s1);
                    s2 = ffma2(wc[2 * i], x0, s2);
                    s2 = ffma2(wc[2 * i + 1], x1, s2);
                }
                float a0 = warpsum(f2sum(s0));
                float a1 = warpsum(f2sum(s1));
                float a2 = warpsum(f2sum(s2));
                if (lane == 0) {
                    size_t o = (size_t)(c * 16 + v) * G4 + r;
                    g_xproj[o]     = a0 + bs0;
                    g_xproj[o + 1] = a1 + bs1;
                    g_xproj[o + 2] = a2 + bs2;
                }
            }
        }
    }

    grid_sync(b, base + 1);

    // ======== 48-step controller loop ========
    for (int t = 0; t < TT; t++) {
        const int par = t & 1;
        const int rb = t % 3, wb2 = (t + 1) % 3, zb = (t + 2) % 3;

        // ---- loads: logits FIRST (softmax gates the chain) ----
        float lg = 0.f;
        if (t > 0) lg = g_log3[rb][lane * LSTR] + bout[(t - 1) * SS + lane];
        float a0[KU], a1[KU], a2[KU], a3[KU], cc[KU];
        #pragma unroll
        for (int k = 0; k < KU; k++) {
            int u = tid + k * NT;
            sV[HH + u] = g_h2[par][u];          // stage h2(t-1)
            if (t > 0) {
                a0[k] = g_g1[par][u];          a1[k] = g_g1[par][HH + u];
                a2[k] = g_g1[par][2 * HH + u]; a3[k] = g_g1[par][3 * HH + u];
                cc[k] = g_c1[par][u];
            } else {
                a0[k] = a1[k] = a2[k] = a3[k] = cc[k] = 0.f;
            }
        }
        if (tid < SS * UPB) {   // fp32 head slice for this block's units
            int s = tid / UPB, j = tid % UPB;
            sWo[tid] = __ldg(&Wout[((size_t)t * SS + s) * HH + u0 + j]);
        }

        // ---- per-warp redundant softmax/argmax of step t-1 (shfl-only) ----
        int sid;
        if (t > 0) {
            float v = lg;
            float bv = v; int bi = lane;
            #pragma unroll
            for (int o = 16; o; o >>= 1) {
                float ov = __shfl_xor_sync(0xffffffffu, bv, o);
                int   oi = __shfl_xor_sync(0xffffffffu, bi, o);
                if (ov > bv || (ov == bv && oi < bi)) { bv = ov; bi = oi; }
            }
            float e = expf(v - bv), se = e;
            #pragma unroll
            for (int o = 16; o; o >>= 1) se += __shfl_xor_sync(0xffffffffu, se, o);
            float lse = bv + logf(se);
            if (b == 0 && w == 0) out[(t - 1) * SS + lane] = v - lse;
            sid = ((t - 1) & 3) * SS + bi;
        } else {
            sid = *input_id;
        }

        // ---- xproj prefetch, then h1 build (both pre-sync) ----
        {
            const float* xp = g_xproj + (size_t)sid * G4;
            float xg0[KU], xg1[KU], xg2[KU], xg3[KU];
            #pragma unroll
            for (int k = 0; k < KU; k++) {
                int u = tid + k * NT;
                xg0[k] = __ldg(&xp[u]);
                xg1[k] = __ldg(&xp[HH + u]);
                xg2[k] = __ldg(&xp[2 * HH + u]);
                xg3[k] = __ldg(&xp[3 * HH + u]);
            }
            #pragma unroll
            for (int k = 0; k < KU; k++) {
                int u = tid + k * NT;
                float gi = a0[k] + xg0[k];
                float gf = a1[k] + xg1[k];
                float gg = a2[k] + xg2[k];
                float go = a3[k] + xg3[k];
                float cn = fsigm(gf) * cc[k] + fsigm(gi) * ftanh(gg);
                sV[u] = fsigm(go) * ftanh(cn);
                if (u >= u0 && u < u0 + UPB) g_c1[par ^ 1][u] = cn;
            }
        }
        __syncthreads();   // h1 + h2 staged -> megadot

        // ---- MEGADOT: all 9 rows in one pass (11 load streams) ----
        float accA[3], accC[3];
        dot9_acc<6>(w2base, w1base, sV, sV + HH, lane, accA, accC);
        accA[0] = warpsum(accA[0]);
        accA[1] = warpsum(accA[1]);
        accA[2] = warpsum(accA[2]);
        accC[0] = warpsum(accC[0]);
        accC[1] = warpsum(accC[1]);
        accC[2] = warpsum(accC[2]);
        if (lane == 0) {
            sG[l0]     = accA[0] + bsum0;
            sG[l0 + 1] = accA[1] + bsum1;
            sG[l0 + 2] = accA[2] + bsum2;
            g_g1[par ^ 1][r1row]     = accC[0];
            g_g1[par ^ 1][r1row + 1] = accC[1];
            g_g1[par ^ 1][r1row + 2] = accC[2];
        }
        __syncthreads();

        // ---- finalize own h2 units + partial logits -> spread atomics ----
        if (w == 0) {
            float hn = 0.f;
            if (lane < UPB) {
                int u = u0 + lane;
                float gi = sG[lane],           gf = sG[UPB + lane];
                float gg = sG[2 * UPB + lane], go = sG[3 * UPB + lane];
                float c  = g_c2[u];
                float cn = fsigm(gf) * c + fsigm(gi) * ftanh(gg);
                g_c2[u]          = cn;
                hn               = fsigm(go) * ftanh(cn);
                g_h2[par ^ 1][u] = hn;
            }
            float p = 0.f;
            #pragma unroll
            for (int j = 0; j < UPB; j++) {
                float hj = __shfl_sync(0xffffffffu, hn, j);
                p = fmaf(sWo[lane * UPB + j], hj, p);
            }
            atomicAdd(&g_log3[wb2][lane * LSTR], p);
        }
        if (b == 0 && w == 1) g_log3[zb][lane * LSTR] = 0.0f;  // recycle buffer

        grid_sync(b, base + 2 + (unsigned)t);
    }

    // epilogue: logp(47) from g_log3[48%3 = 0]
    if (b == 0 && w == 0) {
        float v = g_log3[0][lane * LSTR] + bout[47 * SS + lane];
        float m = v;
        #pragma unroll
        for (int o = 16; o; o >>= 1) m = fmaxf(m, __shfl_xor_sync(0xffffffffu, m, o));
        float e = expf(v - m), se = e;
        #pragma unroll
        for (int o = 16; o; o >>= 1) se += __shfl_xor_sync(0xffffffffu, se, o);
        float lse = m + logf(se);
        out[47 * SS + lane] = v - lse;
    }
}

extern "C" void kernel_launch(void* const* d_in, const int* in_sizes, int n_in,
                              void* d_out, int out_size) {
    const int*   input_id = (const int*)  d_in[0];
    const float* emb      = (const float*)d_in[1];
    const float* W_ih1    = (const float*)d_in[2];
    const float* W_hh1    = (const float*)d_in[3];
    const float* b_ih1    = (const float*)d_in[4];
    const float* b_hh1    = (const float*)d_in[5];
    const float* W_ih2    = (const float*)d_in[6];
    const float* W_hh2    = (const float*)d_in[7];
    const float* b_ih2    = (const float*)d_in[8];
    const float* b_hh2    = (const float*)d_in[9];
    const float* W_out    = (const float*)d_in[10];
    const float* b_out    = (const float*)d_in[11];
    float* out = (float*)d_out;

    nas_all<<<NB, NT>>>(input_id, emb, W_ih1, W_hh1, b_ih1, b_hh1,
                        W_ih2, W_hh2, b_ih2, b_hh2, W_out, b_out, out);
}